// round 3
// baseline (speedup 1.0000x reference)
#include <cuda_runtime.h>
#include <cuda_bf16.h>
#include <math.h>

// Problem constants (fixed by setup_inputs): x,y [1,16,256,512] f32,
// depth [1,32,256,512] f32, out [1,32,32,256,512] f32.
constexpr int C_  = 16;
constexpr int H_  = 256;
constexpr int W_  = 512;
constexpr int ND_ = 32;
constexpr int HW_  = H_ * W_;          // 131072
constexpr int CHS_ = ND_ * H_ * W_;    // out channel stride = 4194304
constexpr float PI_F = 3.14159265358979323846f;
constexpr float BASELINE_F = 0.24f;

__global__ void __launch_bounds__(256)
cost_volume_kernel(const float* __restrict__ x,
                   const float* __restrict__ y,
                   const float* __restrict__ depth,
                   float* __restrict__ out)
{
    int idx = blockIdx.x * blockDim.x + threadIdx.x;   // over ND*H*W
    if (idx >= ND_ * HW_) return;

    int w = idx & (W_ - 1);
    int h = (idx >> 9) & (H_ - 1);     // W_=512=2^9

    // depth streamed exactly once -> .cs
    float dep = __ldcs(depth + idx);

    // theta per row (equirectangular, pixel-centered)
    float theta = ((float)h + 0.5f) * (PI_F / (float)H_) - 0.5f * PI_F;
    float st, ct;
    sincosf(theta, &st, &ct);

    // dtheta_vertical -> pixel rows
    float d_v = (atanf(fmaf(dep, st, BASELINE_F) / (dep * ct)) - theta)
                * ((float)H_ / PI_F);
    float y_px = isfinite(d_v) ? (float)h + d_v : 0.0f;

    // grid_sample bilinear, zeros padding, align_corners=False unnormalize of
    // align_corners=True-style normalized coords:
    //   ix = u * W/(W-1) - 0.5 ,  iy = y_px * H/(H-1) - 0.5
    float ix = (float)w * ((float)W_ / (float)(W_ - 1)) - 0.5f;
    float iy = y_px     * ((float)H_ / (float)(H_ - 1)) - 0.5f;

    float x0f = floorf(ix), y0f = floorf(iy);
    float wx1 = ix - x0f,   wy1 = iy - y0f;
    float wx0 = 1.0f - wx1, wy0 = 1.0f - wy1;

    int x0 = (int)x0f, y0 = (int)y0f;
    int x1 = x0 + 1,   y1 = y0 + 1;

    float vx0 = (x0 >= 0 && x0 < W_) ? 1.0f : 0.0f;
    float vx1 = (x1 >= 0 && x1 < W_) ? 1.0f : 0.0f;
    float vy0 = (y0 >= 0 && y0 < H_) ? 1.0f : 0.0f;
    float vy1 = (y1 >= 0 && y1 < H_) ? 1.0f : 0.0f;

    float w00 = wx0 * wy0 * (vx0 * vy0);
    float w01 = wx1 * wy0 * (vx1 * vy0);
    float w10 = wx0 * wy1 * (vx0 * vy1);
    float w11 = wx1 * wy1 * (vx1 * vy1);

    int xc0 = min(max(x0, 0), W_ - 1);
    int xc1 = min(max(x1, 0), W_ - 1);
    int yc0 = min(max(y0, 0), H_ - 1);
    int yc1 = min(max(y1, 0), H_ - 1);

    int o00 = yc0 * W_ + xc0;
    int o01 = yc0 * W_ + xc1;
    int o10 = yc1 * W_ + xc0;
    int o11 = yc1 * W_ + xc1;

    const float* xp = x + h * W_ + w;
    float* op = out + idx;

    #pragma unroll 4
    for (int cc = 0; cc < C_; cc++) {
        // ref half: broadcast x over disparity (x resident in L2)
        __stcs(op + cc * CHS_, __ldg(xp + cc * HW_));

        // warped half: 4-corner bilinear gather from y (L2-resident)
        const float* yb = y + cc * HW_;
        float v = w00 * __ldg(yb + o00) + w01 * __ldg(yb + o01)
                + w10 * __ldg(yb + o10) + w11 * __ldg(yb + o11);
        __stcs(op + (C_ + cc) * CHS_, v);
    }
}

extern "C" void kernel_launch(void* const* d_in, const int* in_sizes, int n_in,
                              void* d_out, int out_size)
{
    const float* x     = (const float*)d_in[0];
    const float* y     = (const float*)d_in[1];
    const float* depth = (const float*)d_in[2];
    float* out = (float*)d_out;

    const int total = ND_ * HW_;                 // 4,194,304 threads
    const int threads = 256;
    const int blocks = (total + threads - 1) / threads;
    cost_volume_kernel<<<blocks, threads>>>(x, y, depth, out);
}

// round 4
// speedup vs baseline: 1.0947x; 1.0947x over previous
#include <cuda_runtime.h>
#include <cuda_bf16.h>
#include <math.h>

// Problem constants (fixed): x,y [1,16,256,512] f32, depth [1,32,256,512] f32,
// out [1,32,32,256,512] f32.
constexpr int C_  = 16;
constexpr int H_  = 256;
constexpr int W_  = 512;
constexpr int ND_ = 32;
constexpr int HW_  = H_ * W_;          // 131072
constexpr int CHS_ = ND_ * H_ * W_;    // out channel stride = 4194304
constexpr float PI_F = 3.14159265358979323846f;
constexpr float BASELINE_F = 0.24f;

// 8 MB scratch: horizontally-interpolated y, layout [C][H][W].
// The horizontal lerp (ix, wx1, x-validity) depends only on w, so it is
// shared by all 32 disparities and both vertical corners -> precompute once.
__device__ alignas(128) float g_yh[C_ * H_ * W_];

// ---------------------------------------------------------------------------
// Kernel 1: horizontal lerp of y into g_yh.  2M threads, ~16 MB traffic.
// ---------------------------------------------------------------------------
__global__ void __launch_bounds__(256)
hlerp_kernel(const float* __restrict__ y)
{
    int idx = blockIdx.x * blockDim.x + threadIdx.x;   // over C*H*W
    if (idx >= C_ * HW_) return;

    int w = idx & (W_ - 1);
    int rowbase = idx - w;

    // ix = u * W/(W-1) - 0.5  (align_corners=False unnormalize of u/((W-1)/2)-1)
    float ix = (float)w * ((float)W_ / (float)(W_ - 1)) - 0.5f;
    float x0f = floorf(ix);
    float wx1 = ix - x0f;
    float wx0 = 1.0f - wx1;
    int x0 = (int)x0f;
    int x1 = x0 + 1;

    float vx0 = (x0 >= 0 && x0 < W_) ? 1.0f : 0.0f;
    float vx1 = (x1 >= 0 && x1 < W_) ? 1.0f : 0.0f;
    int xc0 = min(max(x0, 0), W_ - 1);
    int xc1 = min(max(x1, 0), W_ - 1);

    float v = (wx0 * vx0) * __ldg(y + rowbase + xc0)
            + (wx1 * vx1) * __ldg(y + rowbase + xc1);
    g_yh[idx] = v;
}

// ---------------------------------------------------------------------------
// Kernel 2: vertical 2-tap lerp + ref broadcast.  One thread per (d,h,w).
// ---------------------------------------------------------------------------
__global__ void __launch_bounds__(256)
cost_volume_kernel(const float* __restrict__ x,
                   const float* __restrict__ depth,
                   float* __restrict__ out)
{
    int idx = blockIdx.x * blockDim.x + threadIdx.x;   // over ND*H*W
    if (idx >= ND_ * HW_) return;

    int w = idx & (W_ - 1);
    int h = (idx >> 9) & (H_ - 1);     // W_=512=2^9

    // depth streamed exactly once
    float dep = __ldcs(depth + idx);

    // theta per row (equirectangular, pixel-centered)
    float theta = ((float)h + 0.5f) * (PI_F / (float)H_) - 0.5f * PI_F;
    float st, ct;
    sincosf(theta, &st, &ct);

    // dtheta_vertical -> pixel rows
    float d_v = (atanf(fmaf(dep, st, BASELINE_F) / (dep * ct)) - theta)
                * ((float)H_ / PI_F);
    float y_px = isfinite(d_v) ? (float)h + d_v : 0.0f;

    // vertical unnormalize: iy = y_px * H/(H-1) - 0.5
    float iy = y_px * ((float)H_ / (float)(H_ - 1)) - 0.5f;
    float y0f = floorf(iy);
    float wy1 = iy - y0f;
    float wy0 = 1.0f - wy1;
    int y0 = (int)y0f;
    int y1 = y0 + 1;

    float vy0 = (y0 >= 0 && y0 < H_) ? 1.0f : 0.0f;
    float vy1 = (y1 >= 0 && y1 < H_) ? 1.0f : 0.0f;
    float wA = wy0 * vy0;
    float wB = wy1 * vy1;

    int kA = min(max(y0, 0), H_ - 1);
    int kB = min(max(y1, 0), H_ - 1);

    int oA = kA * W_ + w;
    int oB = kB * W_ + w;

    const float* xp = x + h * W_ + w;
    float* op = out + idx;

    #pragma unroll
    for (int cc = 0; cc < C_; cc++) {
        // ref half: broadcast x over disparity (x resident in L2/L1)
        __stcs(op + cc * CHS_, __ldg(xp + cc * HW_));

        // warped half: vertical 2-tap lerp of precomputed horizontal lerp
        const float* yb = g_yh + cc * HW_;
        float v = wA * __ldg(yb + oA) + wB * __ldg(yb + oB);
        __stcs(op + (C_ + cc) * CHS_, v);
    }
}

extern "C" void kernel_launch(void* const* d_in, const int* in_sizes, int n_in,
                              void* d_out, int out_size)
{
    const float* x     = (const float*)d_in[0];
    const float* y     = (const float*)d_in[1];
    const float* depth = (const float*)d_in[2];
    float* out = (float*)d_out;

    const int threads = 256;

    // Kernel 1: horizontal precompute (2M threads)
    hlerp_kernel<<<(C_ * HW_ + threads - 1) / threads, threads>>>(y);

    // Kernel 2: main cost volume (4.19M threads)
    cost_volume_kernel<<<(ND_ * HW_ + threads - 1) / threads, threads>>>(x, depth, out);
}